// round 3
// baseline (speedup 1.0000x reference)
#include <cuda_runtime.h>
#include <cstdint>

typedef unsigned int u32;

#define BB 8
#define NN 16384
#define DD 64
#define NCMAX 512
#define EPSF 0.1f
#define TPB 1024
#define PT 16
#define WARPS 32
#define HSTRIDE 257
#define NROWS (BB*DD)

__device__ float g_featT[(size_t)BB*DD*NN];   // (b, d, n) transposed features
__device__ short g_lab[(size_t)BB*DD*NN];     // per-point local labels
__device__ int   g_ncl[NROWS];
__device__ int   g_off[NROWS];

__device__ __forceinline__ u32 f2u(float f){
    u32 u = __float_as_uint(f);
    return (u & 0x80000000u) ? ~u : (u | 0x80000000u);
}
__device__ __forceinline__ float u2f(u32 u){
    u32 v = (u & 0x80000000u) ? (u & 0x7fffffffu) : ~u;
    return __uint_as_float(v);
}
__device__ __forceinline__ float posInf(){ return __int_as_float(0x7f800000); }
__device__ __forceinline__ float negInf(){ return __int_as_float((int)0xff800000); }

// first idx with a[idx] > v
__device__ __forceinline__ int upperBound(const float* a, int n, float v){
    int lo = 0, hi = n;
    while (lo < hi){ int m = (lo + hi) >> 1; if (a[m] <= v) lo = m + 1; else hi = m; }
    return lo;
}
// first idx with a[idx] >= v
__device__ __forceinline__ int lowerBound(const float* a, int n, float v){
    int lo = 0, hi = n;
    while (lo < hi){ int m = (lo + hi) >> 1; if (a[m] < v) lo = m + 1; else hi = m; }
    return lo;
}

// ---------------- warp scans ----------------
__device__ __forceinline__ u32 warpInclAdd(u32 v){
    int lane = threadIdx.x & 31;
    #pragma unroll
    for (int o = 1; o < 32; o <<= 1){
        u32 t = __shfl_up_sync(0xffffffffu, v, o);
        if (lane >= o) v += t;
    }
    return v;
}
__device__ __forceinline__ int warpInclMax(int v){
    int lane = threadIdx.x & 31;
    #pragma unroll
    for (int o = 1; o < 32; o <<= 1){
        int t = __shfl_up_sync(0xffffffffu, v, o);
        if (lane >= o) v = max(v, t);
    }
    return v;
}
__device__ __forceinline__ int warpInclMin(int v){
    int lane = threadIdx.x & 31;
    #pragma unroll
    for (int o = 1; o < 32; o <<= 1){
        int t = __shfl_up_sync(0xffffffffu, v, o);
        if (lane >= o) v = min(v, t);
    }
    return v;
}

// ---------------- block scans (1024 threads, all must call) ----------------
__device__ u32 blkExclAdd(u32 v, int* tmp, u32* total){
    int lane = threadIdx.x & 31, w = threadIdx.x >> 5;
    u32 inc = warpInclAdd(v);
    if (lane == 31) tmp[w] = (int)inc;
    __syncthreads();
    if (w == 0){
        u32 t = (u32)tmp[lane];
        u32 ti = warpInclAdd(t);
        tmp[lane] = (int)ti;
    }
    __syncthreads();
    u32 carry = (w > 0) ? (u32)tmp[w-1] : 0u;
    if (total) *total = (u32)tmp[31];
    u32 res = carry + inc - v;
    __syncthreads();
    return res;
}
__device__ int blkExclMax(int v, int* tmp){   // identity -1
    int lane = threadIdx.x & 31, w = threadIdx.x >> 5;
    int inc = warpInclMax(v);
    int ex = __shfl_up_sync(0xffffffffu, inc, 1);
    if (lane == 0) ex = -1;
    if (lane == 31) tmp[w] = inc;
    __syncthreads();
    if (w == 0){
        int t = tmp[lane];
        int ti = warpInclMax(t);
        tmp[lane] = ti;
    }
    __syncthreads();
    int carry = (w > 0) ? tmp[w-1] : -1;
    int res = max(carry, ex);
    __syncthreads();
    return res;
}
__device__ int blkExclMin(int v, int* tmp){   // identity NN
    int lane = threadIdx.x & 31, w = threadIdx.x >> 5;
    int inc = warpInclMin(v);
    int ex = __shfl_up_sync(0xffffffffu, inc, 1);
    if (lane == 0) ex = NN;
    if (lane == 31) tmp[w] = inc;
    __syncthreads();
    if (w == 0){
        int t = tmp[lane];
        int ti = warpInclMin(t);
        tmp[lane] = ti;
    }
    __syncthreads();
    int carry = (w > 0) ? tmp[w-1] : NN;
    int res = min(carry, ex);
    __syncthreads();
    return res;
}
// reverse exclusive min: for thread t, min over threads t' > t
__device__ int blkRevExclMin(int v, int* tmp, int* xch){
    int t = threadIdx.x;
    xch[(TPB-1) - t] = v; __syncthreads();
    int rv = xch[t];       __syncthreads();
    int e = blkExclMin(rv, tmp);
    xch[t] = e;            __syncthreads();
    int r = xch[(TPB-1) - t]; __syncthreads();
    return r;
}

// ---------------- transpose: (B,N,D) -> (B,D,N) ----------------
__global__ void transpose_kernel(const float* __restrict__ feat){
    __shared__ float tile[32][33];
    int b  = blockIdx.z;
    int d0 = blockIdx.y * 32;
    int n0 = blockIdx.x * 32;
    int tx = threadIdx.x, ty = threadIdx.y;
    tile[ty][tx] = feat[((size_t)b*NN + (n0+ty))*DD + (d0+tx)];
    __syncthreads();
    g_featT[((size_t)b*DD + (d0+ty))*NN + (n0+tx)] = tile[tx][ty];
}

// ---------------- main DBSCAN kernel: one block per (b,d) ----------------
struct SSmem {
    u32 bufA[NN];
    u32 bufB[NN];
    u32 bufC[NN];    // radix hist during sort (HSTRIDE*32 used); cid after
    int xch[TPB];
    int tmp[WARPS+1];
};

__global__ void __launch_bounds__(TPB, 1) dbscan_kernel(){
    extern __shared__ char smemRaw[];
    SSmem* S = reinterpret_cast<SSmem*>(smemRaw);
    int row = blockIdx.x;
    const float* __restrict__ xrow = g_featT + (size_t)row * NN;
    int tid = threadIdx.x, lane = tid & 31, w = tid >> 5;
    u32 laneLT = (1u << lane) - 1u;

    // load + monotone transform
    for (int i = tid; i < NN; i += TPB) S->bufA[i] = f2u(xrow[i]);
    __syncthreads();

    u32* src = S->bufA;
    u32* dst = S->bufB;
    u32* hist = S->bufC;        // [warp][digit], stride HSTRIDE

    for (int pass = 0; pass < 4; ++pass){
        int shift = pass * 8;
        for (int i = tid; i < HSTRIDE*WARPS; i += TPB) hist[i] = 0;
        __syncthreads();
        int base = w * (32*PT);
        u32* wh = hist + w * HSTRIDE;

        // phase 1: histogram only (no per-element state kept)
        #pragma unroll
        for (int j = 0; j < PT; ++j){
            u32 k = src[base + j*32 + lane];
            u32 dg = (k >> shift) & 255u;
            u32 peers = __match_any_sync(0xffffffffu, dg);
            if ((peers & laneLT) == 0u)      // leader (lowest lane of group)
                wh[dg] += (u32)__popc(peers);
            __syncwarp();
        }
        __syncthreads();

        // exclusive scan of counters in (digit-major, warp-minor) order
        {
            u32 v[8]; u32 s = 0;
            int o = tid * 8;
            #pragma unroll
            for (int k2 = 0; k2 < 8; ++k2){
                int oo = o + k2;
                v[k2] = hist[(oo & 31)*HSTRIDE + (oo >> 5)];
            }
            #pragma unroll
            for (int k2 = 0; k2 < 8; ++k2){ u32 t2 = s; s += v[k2]; v[k2] = t2; }
            u32 carry = blkExclAdd(s, S->tmp, 0);
            #pragma unroll
            for (int k2 = 0; k2 < 8; ++k2){
                int oo = o + k2;
                hist[(oo & 31)*HSTRIDE + (oo >> 5)] = v[k2] + carry;
            }
        }
        __syncthreads();

        // phase 2: recompute rank against scanned bases, scatter directly
        #pragma unroll
        for (int j = 0; j < PT; ++j){
            u32 k = src[base + j*32 + lane];
            u32 dg = (k >> shift) & 255u;
            u32 peers = __match_any_sync(0xffffffffu, dg);
            int leader = __ffs(peers) - 1;
            u32 before = (u32)__popc(peers & laneLT);
            u32 old = 0;
            if (before == 0u){
                old = wh[dg];
                wh[dg] = old + (u32)__popc(peers);
            }
            old = __shfl_sync(0xffffffffu, old, leader);
            dst[old + before] = k;
            __syncwarp();
        }
        __syncthreads();
        u32* t3 = src; src = dst; dst = t3;
    }
    // after 4 passes sorted data is back in bufA (== src)
    float* xs = reinterpret_cast<float*>(src);
    for (int i = tid; i < NN; i += TPB){
        u32 u = src[i];
        xs[i] = u2f(u);
    }
    __syncthreads();

    // ---- core test with per-thread two-pointer ----
    int p0 = tid * PT;
    u32 coreMask = 0;
    {
        float x0 = xs[p0];
        int hi = upperBound(xs, NN, x0 + EPSF);
        int lo = lowerBound(xs, NN, x0 - EPSF);
        #pragma unroll
        for (int e = 0; e < PT; ++e){
            float x = xs[p0 + e];
            float a = x + EPSF, bnd = x - EPSF;
            while (hi < NN && xs[hi] <= a) ++hi;
            while (lo < NN && xs[lo] <  bnd) ++lo;
            if (hi - lo >= 5) coreMask |= (1u << e);
        }
    }

    // per-thread summaries
    int localPrev = -1, localNext = NN;
    #pragma unroll
    for (int e = 0; e < PT; ++e) if (coreMask & (1u << e)) localPrev = p0 + e;
    #pragma unroll
    for (int e = PT-1; e >= 0; --e) if (coreMask & (1u << e)) localNext = p0 + e;

    int carryP = blkExclMax(localPrev, S->tmp);
    int carryN = blkRevExclMin(localNext, S->tmp, S->xch);

    // new-cluster flags + local count
    u32 ncMask = 0;
    {
        int runP = carryP;
        #pragma unroll
        for (int e = 0; e < PT; ++e){
            if (coreMask & (1u << e)){
                float x = xs[p0 + e];
                float pv = (runP >= 0) ? xs[runP] : negInf();
                if (x - pv > EPSF) ncMask |= (1u << e);
                runP = p0 + e;
            }
        }
    }
    u32 total = 0;
    u32 carryC = blkExclAdd((u32)__popc(ncMask), S->tmp, &total);

    // write cid array (bufC reused)
    int* cid = reinterpret_cast<int*>(S->bufC);
    {
        int c = (int)carryC;
        #pragma unroll
        for (int e = 0; e < PT; ++e){
            if (ncMask & (1u << e)) ++c;
            cid[p0 + e] = c - 1;
        }
    }
    __syncthreads();

    // labels per sorted position — two streaming passes, no register arrays
    int* lab = reinterpret_cast<int*>(S->bufB);
    {
        // reverse pass: next core index (inclusive) -> lab temp
        int rN = carryN;
        #pragma unroll
        for (int e = PT-1; e >= 0; --e){
            int idx = p0 + e;
            if (coreMask & (1u << e)) rN = idx;
            lab[idx] = rN;
        }
        // forward pass: final labels
        int rP = carryP;
        #pragma unroll
        for (int e = 0; e < PT; ++e){
            int idx = p0 + e;
            int l;
            if (coreMask & (1u << e)){
                rP = idx;
                l = cid[idx];
            } else {
                int ni = lab[idx];
                float x = xs[idx];
                float lv = (rP >= 0) ? xs[rP]  : negInf();
                float rv = (ni < NN) ? xs[ni]  : posInf();
                float dl = x - lv, dr = rv - x;
                int lc = (rP >= 0) ? cid[rP] : -1;
                int rc = (ni < NN) ? cid[ni] : -1;
                int bc = (dl <= dr) ? lc : rc;
                l = (fminf(dl, dr) <= EPSF) ? bc : -1;
            }
            lab[idx] = l;
        }
    }
    __syncthreads();

    // lookup: label of each original point via lower_bound on its value
    for (int i = tid; i < NN; i += TPB){
        float x = xrow[i];
        int pos = lowerBound(xs, NN, x);
        g_lab[(size_t)row*NN + i] = (short)lab[pos];
    }
    if (tid == 0) g_ncl[row] = (int)total;
}

// ---------------- offsets: exclusive prefix of ncl over dims ----------------
__global__ void offsets_kernel(){
    int b = threadIdx.x;
    if (b < BB){
        int s = 0;
        for (int d = 0; d < DD; ++d){
            g_off[b*DD + d] = s;
            s += g_ncl[b*DD + d];
        }
    }
}

// ---------------- output: register bitmap via REDUX, streaming stores ------
__global__ void __launch_bounds__(256) output_kernel(float* __restrict__ out){
    __shared__ short labT[DD][66];     // padded: per-lane column reads conflict-free
    __shared__ int offs[DD];
    int b  = blockIdx.y;
    int n0 = blockIdx.x * 64;
    int tid = threadIdx.x, w = tid >> 5, lane = tid & 31;

    for (int l = tid; l < DD*64; l += 256){
        int d = l >> 6, i = l & 63;
        labT[d][i] = g_lab[((size_t)(b*DD + d))*NN + n0 + i];
    }
    if (tid < DD) offs[tid] = g_off[b*DD + tid];
    __syncthreads();

    int q = lane >> 3;                 // which word-of-4 this lane expands
    for (int i = w; i < 64; i += 8){
        int lb0 = labT[lane][i];
        int lb1 = labT[lane + 32][i];
        int g0 = -1, g1 = -1;
        if (lb0 >= 0){ int g = lb0 + offs[lane];      if (g < NCMAX) g0 = g; }
        if (lb1 >= 0){ int g = lb1 + offs[lane + 32]; if (g < NCMAX) g1 = g; }
        u32 myw[4];
        #pragma unroll
        for (int wi = 0; wi < 16; ++wi){
            u32 c = 0;
            if ((g0 >> 5) == wi) c |= 1u << (g0 & 31);
            if ((g1 >> 5) == wi) c |= 1u << (g1 & 31);
            u32 word = __reduce_or_sync(0xffffffffu, c);
            if (q == (wi & 3)) myw[wi >> 2] = word;
        }
        float4* op = reinterpret_cast<float4*>(out + ((size_t)(b*NN + n0 + i))*NCMAX);
        int sh = (lane & 7) * 4;
        #pragma unroll
        for (int k = 0; k < 4; ++k){
            u32 word = myw[k];
            float4 v;
            v.x = (word >> (sh + 0)) & 1u ? 1.0f : 0.0f;
            v.y = (word >> (sh + 1)) & 1u ? 1.0f : 0.0f;
            v.z = (word >> (sh + 2)) & 1u ? 1.0f : 0.0f;
            v.w = (word >> (sh + 3)) & 1u ? 1.0f : 0.0f;
            __stcs(op + k*32 + lane, v);
        }
    }
}

extern "C" void kernel_launch(void* const* d_in, const int* in_sizes, int n_in,
                              void* d_out, int out_size){
    const float* feat = (const float*)d_in[0];
    float* out = (float*)d_out;
    (void)in_sizes; (void)n_in; (void)out_size;

    cudaFuncSetAttribute(dbscan_kernel,
                         cudaFuncAttributeMaxDynamicSharedMemorySize,
                         (int)sizeof(SSmem));

    transpose_kernel<<<dim3(NN/32, DD/32, BB), dim3(32, 32)>>>(feat);
    dbscan_kernel<<<NROWS, TPB, sizeof(SSmem)>>>();
    offsets_kernel<<<1, 32>>>();
    output_kernel<<<dim3(NN/64, BB), 256>>>(out);
}

// round 4
// speedup vs baseline: 1.3081x; 1.3081x over previous
#include <cuda_runtime.h>
#include <cstdint>

typedef unsigned int u32;

#define BB 8
#define NN 16384
#define DD 64
#define NCMAX 512
#define EPSF 0.1f
#define TPB 1024
#define PT 16
#define WARPS 32
#define HSTRIDE 257
#define NROWS (BB*DD)

__device__ float g_featT[(size_t)BB*DD*NN];   // (b, d, n) transposed features
__device__ short g_lab[(size_t)BB*DD*NN];     // per-point local labels
__device__ int   g_ncl[NROWS];
__device__ int   g_off[NROWS];

__device__ __forceinline__ u32 f2u(float f){
    u32 u = __float_as_uint(f);
    return (u & 0x80000000u) ? ~u : (u | 0x80000000u);
}
__device__ __forceinline__ float u2f(u32 u){
    u32 v = (u & 0x80000000u) ? (u & 0x7fffffffu) : ~u;
    return __uint_as_float(v);
}
__device__ __forceinline__ float posInf(){ return __int_as_float(0x7f800000); }
__device__ __forceinline__ float negInf(){ return __int_as_float((int)0xff800000); }

// first idx with a[idx] > v
__device__ __forceinline__ int upperBound(const float* a, int n, float v){
    int lo = 0, hi = n;
    while (lo < hi){ int m = (lo + hi) >> 1; if (a[m] <= v) lo = m + 1; else hi = m; }
    return lo;
}
// first idx with a[idx] >= v
__device__ __forceinline__ int lowerBound(const float* a, int n, float v){
    int lo = 0, hi = n;
    while (lo < hi){ int m = (lo + hi) >> 1; if (a[m] < v) lo = m + 1; else hi = m; }
    return lo;
}

// ---------------- warp scans ----------------
__device__ __forceinline__ u32 warpInclAdd(u32 v){
    int lane = threadIdx.x & 31;
    #pragma unroll
    for (int o = 1; o < 32; o <<= 1){
        u32 t = __shfl_up_sync(0xffffffffu, v, o);
        if (lane >= o) v += t;
    }
    return v;
}
__device__ __forceinline__ int warpInclMax(int v){
    int lane = threadIdx.x & 31;
    #pragma unroll
    for (int o = 1; o < 32; o <<= 1){
        int t = __shfl_up_sync(0xffffffffu, v, o);
        if (lane >= o) v = max(v, t);
    }
    return v;
}
__device__ __forceinline__ int warpInclMin(int v){
    int lane = threadIdx.x & 31;
    #pragma unroll
    for (int o = 1; o < 32; o <<= 1){
        int t = __shfl_up_sync(0xffffffffu, v, o);
        if (lane >= o) v = min(v, t);
    }
    return v;
}

// ---------------- block scans (1024 threads, all must call) ----------------
__device__ u32 blkExclAdd(u32 v, int* tmp, u32* total){
    int lane = threadIdx.x & 31, w = threadIdx.x >> 5;
    u32 inc = warpInclAdd(v);
    if (lane == 31) tmp[w] = (int)inc;
    __syncthreads();
    if (w == 0){
        u32 t = (u32)tmp[lane];
        u32 ti = warpInclAdd(t);
        tmp[lane] = (int)ti;
    }
    __syncthreads();
    u32 carry = (w > 0) ? (u32)tmp[w-1] : 0u;
    if (total) *total = (u32)tmp[31];
    u32 res = carry + inc - v;
    __syncthreads();
    return res;
}
__device__ int blkExclMax(int v, int* tmp){   // identity -1
    int lane = threadIdx.x & 31, w = threadIdx.x >> 5;
    int inc = warpInclMax(v);
    int ex = __shfl_up_sync(0xffffffffu, inc, 1);
    if (lane == 0) ex = -1;
    if (lane == 31) tmp[w] = inc;
    __syncthreads();
    if (w == 0){
        int t = tmp[lane];
        int ti = warpInclMax(t);
        tmp[lane] = ti;
    }
    __syncthreads();
    int carry = (w > 0) ? tmp[w-1] : -1;
    int res = max(carry, ex);
    __syncthreads();
    return res;
}
__device__ int blkExclMin(int v, int* tmp){   // identity NN
    int lane = threadIdx.x & 31, w = threadIdx.x >> 5;
    int inc = warpInclMin(v);
    int ex = __shfl_up_sync(0xffffffffu, inc, 1);
    if (lane == 0) ex = NN;
    if (lane == 31) tmp[w] = inc;
    __syncthreads();
    if (w == 0){
        int t = tmp[lane];
        int ti = warpInclMin(t);
        tmp[lane] = ti;
    }
    __syncthreads();
    int carry = (w > 0) ? tmp[w-1] : NN;
    int res = min(carry, ex);
    __syncthreads();
    return res;
}
// reverse exclusive min: for thread t, min over threads t' > t
__device__ int blkRevExclMin(int v, int* tmp, int* xch){
    int t = threadIdx.x;
    xch[(TPB-1) - t] = v; __syncthreads();
    int rv = xch[t];       __syncthreads();
    int e = blkExclMin(rv, tmp);
    xch[t] = e;            __syncthreads();
    int r = xch[(TPB-1) - t]; __syncthreads();
    return r;
}

// ---------------- transpose: (B,N,D) -> (B,D,N) ----------------
__global__ void transpose_kernel(const float* __restrict__ feat){
    __shared__ float tile[32][33];
    int b  = blockIdx.z;
    int d0 = blockIdx.y * 32;
    int n0 = blockIdx.x * 32;
    int tx = threadIdx.x, ty = threadIdx.y;
    tile[ty][tx] = feat[((size_t)b*NN + (n0+ty))*DD + (d0+tx)];
    __syncthreads();
    g_featT[((size_t)b*DD + (d0+ty))*NN + (n0+tx)] = tile[tx][ty];
}

// ---------------- main DBSCAN kernel: one block per (b,d) ----------------
struct SSmem {
    u32 bufA[NN];
    u32 bufB[NN];
    u32 bufC[NN];    // radix hist during sort (HSTRIDE*32 used); cid after
    int xch[TPB];
    int tmp[WARPS+1];
};

// ballot-based peer mask for 8-bit digit: no MATCH, no divergence
__device__ __forceinline__ u32 peers8(u32 dg){
    u32 peers = 0xffffffffu;
    #pragma unroll
    for (int b2 = 0; b2 < 8; ++b2){
        u32 bit = (dg >> b2) & 1u;
        u32 bal = __ballot_sync(0xffffffffu, bit);
        peers &= bit ? bal : ~bal;
    }
    return peers;
}

__global__ void __launch_bounds__(TPB, 1) dbscan_kernel(){
    extern __shared__ char smemRaw[];
    SSmem* S = reinterpret_cast<SSmem*>(smemRaw);
    int row = blockIdx.x;
    const float* __restrict__ xrow = g_featT + (size_t)row * NN;
    int tid = threadIdx.x, lane = tid & 31, w = tid >> 5;
    u32 laneLT = (1u << lane) - 1u;

    // load + monotone transform
    for (int i = tid; i < NN; i += TPB) S->bufA[i] = f2u(xrow[i]);
    __syncthreads();

    u32* src = S->bufA;
    u32* dst = S->bufB;
    u32* hist = S->bufC;        // [warp][digit], stride HSTRIDE

    for (int pass = 0; pass < 4; ++pass){
        int shift = pass * 8;
        for (int i = tid; i < HSTRIDE*WARPS; i += TPB) hist[i] = 0;
        __syncthreads();
        int base = w * (32*PT);
        u32* wh = hist + w * HSTRIDE;

        // sweep 1: histogram (redundant group update, divergence-free)
        #pragma unroll
        for (int j = 0; j < PT; ++j){
            u32 k = src[base + j*32 + lane];
            u32 dg = (k >> shift) & 255u;
            u32 pe = peers8(dg);
            u32 cnt = (u32)__popc(pe);
            u32 old = wh[dg];          // broadcast within group
            wh[dg] = old + cnt;        // same addr+value within group: collapses
        }
        __syncthreads();

        // exclusive scan of counters in (digit-major, warp-minor) order
        {
            u32 v[8]; u32 s = 0;
            int o = tid * 8;
            #pragma unroll
            for (int k2 = 0; k2 < 8; ++k2){
                int oo = o + k2;
                v[k2] = hist[(oo & 31)*HSTRIDE + (oo >> 5)];
            }
            #pragma unroll
            for (int k2 = 0; k2 < 8; ++k2){ u32 t2 = s; s += v[k2]; v[k2] = t2; }
            u32 carry = blkExclAdd(s, S->tmp, 0);
            #pragma unroll
            for (int k2 = 0; k2 < 8; ++k2){
                int oo = o + k2;
                hist[(oo & 31)*HSTRIDE + (oo >> 5)] = v[k2] + carry;
            }
        }
        __syncthreads();

        // sweep 2: rank against scanned bases, scatter (stable)
        #pragma unroll
        for (int j = 0; j < PT; ++j){
            u32 k = src[base + j*32 + lane];
            u32 dg = (k >> shift) & 255u;
            u32 pe = peers8(dg);
            u32 cnt = (u32)__popc(pe);
            u32 rk  = (u32)__popc(pe & laneLT);
            u32 old = wh[dg];
            wh[dg] = old + cnt;
            dst[old + rk] = k;
        }
        __syncthreads();
        u32* t3 = src; src = dst; dst = t3;
    }
    // after 4 passes sorted data is back in bufA (== src)
    float* xs = reinterpret_cast<float*>(src);
    for (int i = tid; i < NN; i += TPB){
        u32 u = src[i];
        xs[i] = u2f(u);
    }
    __syncthreads();

    // ---- core test with per-thread two-pointer ----
    int p0 = tid * PT;
    u32 coreMask = 0;
    {
        float x0 = xs[p0];
        int hi = upperBound(xs, NN, x0 + EPSF);
        int lo = lowerBound(xs, NN, x0 - EPSF);
        #pragma unroll
        for (int e = 0; e < PT; ++e){
            float x = xs[p0 + e];
            float a = x + EPSF, bnd = x - EPSF;
            while (hi < NN && xs[hi] <= a) ++hi;
            while (lo < NN && xs[lo] <  bnd) ++lo;
            if (hi - lo >= 5) coreMask |= (1u << e);
        }
    }

    // per-thread summaries
    int localPrev = -1, localNext = NN;
    #pragma unroll
    for (int e = 0; e < PT; ++e) if (coreMask & (1u << e)) localPrev = p0 + e;
    #pragma unroll
    for (int e = PT-1; e >= 0; --e) if (coreMask & (1u << e)) localNext = p0 + e;

    int carryP = blkExclMax(localPrev, S->tmp);
    int carryN = blkRevExclMin(localNext, S->tmp, S->xch);

    // new-cluster flags + local count
    u32 ncMask = 0;
    {
        int runP = carryP;
        #pragma unroll
        for (int e = 0; e < PT; ++e){
            if (coreMask & (1u << e)){
                float x = xs[p0 + e];
                float pv = (runP >= 0) ? xs[runP] : negInf();
                if (x - pv > EPSF) ncMask |= (1u << e);
                runP = p0 + e;
            }
        }
    }
    u32 total = 0;
    u32 carryC = blkExclAdd((u32)__popc(ncMask), S->tmp, &total);

    // write cid array (bufC reused)
    int* cid = reinterpret_cast<int*>(S->bufC);
    {
        int c = (int)carryC;
        #pragma unroll
        for (int e = 0; e < PT; ++e){
            if (ncMask & (1u << e)) ++c;
            cid[p0 + e] = c - 1;
        }
    }
    __syncthreads();

    // labels per sorted position — two streaming passes, no register arrays
    int* lab = reinterpret_cast<int*>(S->bufB);
    {
        // reverse pass: next core index (inclusive) -> lab temp
        int rN = carryN;
        #pragma unroll
        for (int e = PT-1; e >= 0; --e){
            int idx = p0 + e;
            if (coreMask & (1u << e)) rN = idx;
            lab[idx] = rN;
        }
        // forward pass: final labels
        int rP = carryP;
        #pragma unroll
        for (int e = 0; e < PT; ++e){
            int idx = p0 + e;
            int l;
            if (coreMask & (1u << e)){
                rP = idx;
                l = cid[idx];
            } else {
                int ni = lab[idx];
                float x = xs[idx];
                float lv = (rP >= 0) ? xs[rP]  : negInf();
                float rv = (ni < NN) ? xs[ni]  : posInf();
                float dl = x - lv, dr = rv - x;
                int lc = (rP >= 0) ? cid[rP] : -1;
                int rc = (ni < NN) ? cid[ni] : -1;
                int bc = (dl <= dr) ? lc : rc;
                l = (fminf(dl, dr) <= EPSF) ? bc : -1;
            }
            lab[idx] = l;
        }
    }
    __syncthreads();

    // lookup: label of each original point via lower_bound on its value
    for (int i = tid; i < NN; i += TPB){
        float x = xrow[i];
        int pos = lowerBound(xs, NN, x);
        g_lab[(size_t)row*NN + i] = (short)lab[pos];
    }
    if (tid == 0) g_ncl[row] = (int)total;
}

// ---------------- offsets: exclusive prefix of ncl over dims ----------------
__global__ void offsets_kernel(){
    int b = threadIdx.x;
    if (b < BB){
        int s = 0;
        for (int d = 0; d < DD; ++d){
            g_off[b*DD + d] = s;
            s += g_ncl[b*DD + d];
        }
    }
}

// ---------------- output: register bitmap via REDUX, streaming stores ------
__global__ void __launch_bounds__(256) output_kernel(float* __restrict__ out){
    __shared__ short labT[DD][66];     // padded: per-lane column reads conflict-free
    __shared__ int offs[DD];
    int b  = blockIdx.y;
    int n0 = blockIdx.x * 64;
    int tid = threadIdx.x, w = tid >> 5, lane = tid & 31;

    for (int l = tid; l < DD*64; l += 256){
        int d = l >> 6, i = l & 63;
        labT[d][i] = g_lab[((size_t)(b*DD + d))*NN + n0 + i];
    }
    if (tid < DD) offs[tid] = g_off[b*DD + tid];
    __syncthreads();

    int q = lane >> 3;                 // which word-of-4 this lane expands
    for (int i = w; i < 64; i += 8){
        int lb0 = labT[lane][i];
        int lb1 = labT[lane + 32][i];
        int g0 = -1, g1 = -1;
        if (lb0 >= 0){ int g = lb0 + offs[lane];      if (g < NCMAX) g0 = g; }
        if (lb1 >= 0){ int g = lb1 + offs[lane + 32]; if (g < NCMAX) g1 = g; }
        u32 myw[4];
        #pragma unroll
        for (int wi = 0; wi < 16; ++wi){
            u32 c = 0;
            if ((g0 >> 5) == wi) c |= 1u << (g0 & 31);
            if ((g1 >> 5) == wi) c |= 1u << (g1 & 31);
            u32 word = __reduce_or_sync(0xffffffffu, c);
            if (q == (wi & 3)) myw[wi >> 2] = word;
        }
        float4* op = reinterpret_cast<float4*>(out + ((size_t)(b*NN + n0 + i))*NCMAX);
        int sh = (lane & 7) * 4;
        #pragma unroll
        for (int k = 0; k < 4; ++k){
            u32 word = myw[k];
            float4 v;
            v.x = (word >> (sh + 0)) & 1u ? 1.0f : 0.0f;
            v.y = (word >> (sh + 1)) & 1u ? 1.0f : 0.0f;
            v.z = (word >> (sh + 2)) & 1u ? 1.0f : 0.0f;
            v.w = (word >> (sh + 3)) & 1u ? 1.0f : 0.0f;
            __stcs(op + k*32 + lane, v);
        }
    }
}

extern "C" void kernel_launch(void* const* d_in, const int* in_sizes, int n_in,
                              void* d_out, int out_size){
    const float* feat = (const float*)d_in[0];
    float* out = (float*)d_out;
    (void)in_sizes; (void)n_in; (void)out_size;

    cudaFuncSetAttribute(dbscan_kernel,
                         cudaFuncAttributeMaxDynamicSharedMemorySize,
                         (int)sizeof(SSmem));

    transpose_kernel<<<dim3(NN/32, DD/32, BB), dim3(32, 32)>>>(feat);
    dbscan_kernel<<<NROWS, TPB, sizeof(SSmem)>>>();
    offsets_kernel<<<1, 32>>>();
    output_kernel<<<dim3(NN/64, BB), 256>>>(out);
}

// round 5
// speedup vs baseline: 1.6984x; 1.2984x over previous
#include <cuda_runtime.h>
#include <cstdint>
#include <cub/block/block_radix_sort.cuh>

typedef unsigned int u32;

#define BB 8
#define NN 16384
#define DD 64
#define NCMAX 512
#define EPSF 0.1f
#define TPB 1024
#define PT 16
#define WARPS 32
#define NROWS (BB*DD)

#define SBT 512
#define SIPT 32

__device__ float g_featT[(size_t)BB*DD*NN];   // (b, d, n) transposed features
__device__ u32   g_sorted[(size_t)BB*DD*NN];  // per-row sorted (monotone u32) keys
__device__ short g_lab[(size_t)BB*DD*NN];     // per-point local labels
__device__ int   g_ncl[NROWS];
__device__ int   g_off[NROWS];

__device__ __forceinline__ u32 f2u(float f){
    u32 u = __float_as_uint(f);
    return (u & 0x80000000u) ? ~u : (u | 0x80000000u);
}
__device__ __forceinline__ float u2f(u32 u){
    u32 v = (u & 0x80000000u) ? (u & 0x7fffffffu) : ~u;
    return __uint_as_float(v);
}
__device__ __forceinline__ float posInf(){ return __int_as_float(0x7f800000); }
__device__ __forceinline__ float negInf(){ return __int_as_float((int)0xff800000); }

// transposed smem index for per-element strided arrays (kills 16-way conflicts)
__device__ __forceinline__ int xpos(int i){ return ((i & (PT-1)) << 10) | (i >> 4); }

// first idx with a[idx] > v
__device__ __forceinline__ int upperBound(const float* a, int n, float v){
    int lo = 0, hi = n;
    while (lo < hi){ int m = (lo + hi) >> 1; if (a[m] <= v) lo = m + 1; else hi = m; }
    return lo;
}
// first idx with a[idx] >= v
__device__ __forceinline__ int lowerBound(const float* a, int n, float v){
    int lo = 0, hi = n;
    while (lo < hi){ int m = (lo + hi) >> 1; if (a[m] < v) lo = m + 1; else hi = m; }
    return lo;
}

// ---------------- warp scans ----------------
__device__ __forceinline__ u32 warpInclAdd(u32 v){
    int lane = threadIdx.x & 31;
    #pragma unroll
    for (int o = 1; o < 32; o <<= 1){
        u32 t = __shfl_up_sync(0xffffffffu, v, o);
        if (lane >= o) v += t;
    }
    return v;
}
__device__ __forceinline__ int warpInclMax(int v){
    int lane = threadIdx.x & 31;
    #pragma unroll
    for (int o = 1; o < 32; o <<= 1){
        int t = __shfl_up_sync(0xffffffffu, v, o);
        if (lane >= o) v = max(v, t);
    }
    return v;
}
__device__ __forceinline__ int warpInclMin(int v){
    int lane = threadIdx.x & 31;
    #pragma unroll
    for (int o = 1; o < 32; o <<= 1){
        int t = __shfl_up_sync(0xffffffffu, v, o);
        if (lane >= o) v = min(v, t);
    }
    return v;
}

// ---------------- block scans (1024 threads, all must call) ----------------
__device__ u32 blkExclAdd(u32 v, int* tmp, u32* total){
    int lane = threadIdx.x & 31, w = threadIdx.x >> 5;
    u32 inc = warpInclAdd(v);
    if (lane == 31) tmp[w] = (int)inc;
    __syncthreads();
    if (w == 0){
        u32 t = (u32)tmp[lane];
        u32 ti = warpInclAdd(t);
        tmp[lane] = (int)ti;
    }
    __syncthreads();
    u32 carry = (w > 0) ? (u32)tmp[w-1] : 0u;
    if (total) *total = (u32)tmp[31];
    u32 res = carry + inc - v;
    __syncthreads();
    return res;
}
__device__ int blkExclMax(int v, int* tmp){   // identity -1
    int lane = threadIdx.x & 31, w = threadIdx.x >> 5;
    int inc = warpInclMax(v);
    int ex = __shfl_up_sync(0xffffffffu, inc, 1);
    if (lane == 0) ex = -1;
    if (lane == 31) tmp[w] = inc;
    __syncthreads();
    if (w == 0){
        int t = tmp[lane];
        int ti = warpInclMax(t);
        tmp[lane] = ti;
    }
    __syncthreads();
    int carry = (w > 0) ? tmp[w-1] : -1;
    int res = max(carry, ex);
    __syncthreads();
    return res;
}
__device__ int blkExclMin(int v, int* tmp){   // identity NN
    int lane = threadIdx.x & 31, w = threadIdx.x >> 5;
    int inc = warpInclMin(v);
    int ex = __shfl_up_sync(0xffffffffu, inc, 1);
    if (lane == 0) ex = NN;
    if (lane == 31) tmp[w] = inc;
    __syncthreads();
    if (w == 0){
        int t = tmp[lane];
        int ti = warpInclMin(t);
        tmp[lane] = ti;
    }
    __syncthreads();
    int carry = (w > 0) ? tmp[w-1] : NN;
    int res = min(carry, ex);
    __syncthreads();
    return res;
}
// reverse exclusive min: for thread t, min over threads t' > t
__device__ int blkRevExclMin(int v, int* tmp, int* xch){
    int t = threadIdx.x;
    xch[(TPB-1) - t] = v; __syncthreads();
    int rv = xch[t];       __syncthreads();
    int e = blkExclMin(rv, tmp);
    xch[t] = e;            __syncthreads();
    int r = xch[(TPB-1) - t]; __syncthreads();
    return r;
}

// ---------------- transpose: (B,N,D) -> (B,D,N) ----------------
__global__ void transpose_kernel(const float* __restrict__ feat){
    __shared__ float tile[32][33];
    int b  = blockIdx.z;
    int d0 = blockIdx.y * 32;
    int n0 = blockIdx.x * 32;
    int tx = threadIdx.x, ty = threadIdx.y;
    tile[ty][tx] = feat[((size_t)b*NN + (n0+ty))*DD + (d0+tx)];
    __syncthreads();
    g_featT[((size_t)b*DD + (d0+ty))*NN + (n0+tx)] = tile[tx][ty];
}

// ---------------- sort: CUB BlockRadixSort, one block per row --------------
typedef cub::BlockRadixSort<u32, SBT, SIPT> BlockSort;

__global__ void __launch_bounds__(SBT) sort_kernel(){
    extern __shared__ char smemRaw[];
    typename BlockSort::TempStorage* ts =
        reinterpret_cast<typename BlockSort::TempStorage*>(smemRaw);
    int row = blockIdx.x;
    const float* __restrict__ xrow = g_featT + (size_t)row * NN;
    int t = threadIdx.x;
    u32 keys[SIPT];
    #pragma unroll
    for (int j = 0; j < SIPT; ++j)
        keys[j] = f2u(xrow[j*SBT + t]);       // striped load (arrangement irrelevant pre-sort)
    BlockSort(*ts).SortBlockedToStriped(keys);
    u32* __restrict__ srow = g_sorted + (size_t)row * NN;
    #pragma unroll
    for (int j = 0; j < SIPT; ++j)
        srow[j*SBT + t] = keys[j];            // coalesced striped store
}

// ---------------- label kernel: one block per row --------------------------
struct LSmem {
    float xs[NN];        // sorted values
    short labS[NN];      // transposed layout (xpos)
    short cidS[NN];      // transposed layout (xpos)
    int xch[TPB];
    int tmp[WARPS+1];
};

__global__ void __launch_bounds__(TPB, 1) label_kernel(){
    extern __shared__ char smemRaw[];
    LSmem* S = reinterpret_cast<LSmem*>(smemRaw);
    int row = blockIdx.x;
    const float* __restrict__ xrow = g_featT + (size_t)row * NN;
    const u32* __restrict__ srow = g_sorted + (size_t)row * NN;
    int tid = threadIdx.x;

    float* xs = S->xs;
    for (int i = tid; i < NN; i += TPB) xs[i] = u2f(srow[i]);
    __syncthreads();

    // ---- core test with per-thread two-pointer ----
    int p0 = tid * PT;
    u32 coreMask = 0;
    {
        float x0 = xs[p0];
        int hi = upperBound(xs, NN, x0 + EPSF);
        int lo = lowerBound(xs, NN, x0 - EPSF);
        #pragma unroll
        for (int e = 0; e < PT; ++e){
            float x = xs[p0 + e];
            float a = x + EPSF, bnd = x - EPSF;
            while (hi < NN && xs[hi] <= a) ++hi;
            while (lo < NN && xs[lo] <  bnd) ++lo;
            if (hi - lo >= 5) coreMask |= (1u << e);
        }
    }

    // per-thread summaries
    int localPrev = -1, localNext = NN;
    #pragma unroll
    for (int e = 0; e < PT; ++e) if (coreMask & (1u << e)) localPrev = p0 + e;
    #pragma unroll
    for (int e = PT-1; e >= 0; --e) if (coreMask & (1u << e)) localNext = p0 + e;

    int carryP = blkExclMax(localPrev, S->tmp);
    int carryN = blkRevExclMin(localNext, S->tmp, S->xch);

    // new-cluster flags + local count
    u32 ncMask = 0;
    {
        int runP = carryP;
        #pragma unroll
        for (int e = 0; e < PT; ++e){
            if (coreMask & (1u << e)){
                float x = xs[p0 + e];
                float pv = (runP >= 0) ? xs[runP] : negInf();
                if (x - pv > EPSF) ncMask |= (1u << e);
                runP = p0 + e;
            }
        }
    }
    u32 total = 0;
    u32 carryC = blkExclAdd((u32)__popc(ncMask), S->tmp, &total);

    // cid per sorted position (transposed short layout)
    short* cid = S->cidS;
    {
        int c = (int)carryC;
        #pragma unroll
        for (int e = 0; e < PT; ++e){
            if (ncMask & (1u << e)) ++c;
            cid[xpos(p0 + e)] = (short)(c - 1);
        }
    }
    __syncthreads();

    // labels per sorted position — two streaming passes
    short* lab = S->labS;
    {
        // reverse pass: next core index (inclusive) stored as temp
        int rN = carryN;
        #pragma unroll
        for (int e = PT-1; e >= 0; --e){
            int idx = p0 + e;
            if (coreMask & (1u << e)) rN = idx;
            lab[xpos(idx)] = (short)rN;
        }
        // forward pass: final labels
        int rP = carryP;
        #pragma unroll
        for (int e = 0; e < PT; ++e){
            int idx = p0 + e;
            int l;
            if (coreMask & (1u << e)){
                rP = idx;
                l = cid[xpos(idx)];
            } else {
                int ni = lab[xpos(idx)];
                float x = xs[idx];
                float lv = (rP >= 0) ? xs[rP]  : negInf();
                float rv = (ni < NN) ? xs[ni]  : posInf();
                float dl = x - lv, dr = rv - x;
                int lc = (rP >= 0) ? cid[xpos(rP)] : -1;
                int rc = (ni < NN) ? cid[xpos(ni)] : -1;
                int bc = (dl <= dr) ? lc : rc;
                l = (fminf(dl, dr) <= EPSF) ? bc : -1;
            }
            lab[xpos(idx)] = (short)l;
        }
    }
    __syncthreads();

    // lookup: label of each original point via lower_bound on its value
    for (int i = tid; i < NN; i += TPB){
        float x = xrow[i];
        int pos = lowerBound(xs, NN, x);
        g_lab[(size_t)row*NN + i] = lab[xpos(pos)];
    }
    if (tid == 0) g_ncl[row] = (int)total;
}

// ---------------- offsets: exclusive prefix of ncl over dims ----------------
__global__ void offsets_kernel(){
    int b = threadIdx.x;
    if (b < BB){
        int s = 0;
        for (int d = 0; d < DD; ++d){
            g_off[b*DD + d] = s;
            s += g_ncl[b*DD + d];
        }
    }
}

// ---------------- output: register bitmap via REDUX, streaming stores ------
__global__ void __launch_bounds__(256) output_kernel(float* __restrict__ out){
    __shared__ short labT[DD][66];
    __shared__ int offs[DD];
    int b  = blockIdx.y;
    int n0 = blockIdx.x * 64;
    int tid = threadIdx.x, w = tid >> 5, lane = tid & 31;

    for (int l = tid; l < DD*64; l += 256){
        int d = l >> 6, i = l & 63;
        labT[d][i] = g_lab[((size_t)(b*DD + d))*NN + n0 + i];
    }
    if (tid < DD) offs[tid] = g_off[b*DD + tid];
    __syncthreads();

    int q = lane >> 3;
    for (int i = w; i < 64; i += 8){
        int lb0 = labT[lane][i];
        int lb1 = labT[lane + 32][i];
        int g0 = -1, g1 = -1;
        if (lb0 >= 0){ int g = lb0 + offs[lane];      if (g < NCMAX) g0 = g; }
        if (lb1 >= 0){ int g = lb1 + offs[lane + 32]; if (g < NCMAX) g1 = g; }
        u32 myw[4];
        #pragma unroll
        for (int wi = 0; wi < 16; ++wi){
            u32 c = 0;
            if ((g0 >> 5) == wi) c |= 1u << (g0 & 31);
            if ((g1 >> 5) == wi) c |= 1u << (g1 & 31);
            u32 word = __reduce_or_sync(0xffffffffu, c);
            if (q == (wi & 3)) myw[wi >> 2] = word;
        }
        float4* op = reinterpret_cast<float4*>(out + ((size_t)(b*NN + n0 + i))*NCMAX);
        int sh = (lane & 7) * 4;
        #pragma unroll
        for (int k = 0; k < 4; ++k){
            u32 word = myw[k];
            float4 v;
            v.x = (word >> (sh + 0)) & 1u ? 1.0f : 0.0f;
            v.y = (word >> (sh + 1)) & 1u ? 1.0f : 0.0f;
            v.z = (word >> (sh + 2)) & 1u ? 1.0f : 0.0f;
            v.w = (word >> (sh + 3)) & 1u ? 1.0f : 0.0f;
            __stcs(op + k*32 + lane, v);
        }
    }
}

extern "C" void kernel_launch(void* const* d_in, const int* in_sizes, int n_in,
                              void* d_out, int out_size){
    const float* feat = (const float*)d_in[0];
    float* out = (float*)d_out;
    (void)in_sizes; (void)n_in; (void)out_size;

    int sortSmem = (int)sizeof(typename BlockSort::TempStorage);
    cudaFuncSetAttribute(sort_kernel,
                         cudaFuncAttributeMaxDynamicSharedMemorySize, sortSmem);
    cudaFuncSetAttribute(label_kernel,
                         cudaFuncAttributeMaxDynamicSharedMemorySize,
                         (int)sizeof(LSmem));

    transpose_kernel<<<dim3(NN/32, DD/32, BB), dim3(32, 32)>>>(feat);
    sort_kernel<<<NROWS, SBT, sortSmem>>>();
    label_kernel<<<NROWS, TPB, sizeof(LSmem)>>>();
    offsets_kernel<<<1, 32>>>();
    output_kernel<<<dim3(NN/64, BB), 256>>>(out);
}